// round 11
// baseline (speedup 1.0000x reference)
#include <cuda_runtime.h>
#include <cstdint>

// ---------------- problem constants ----------------
#define NNZ      220939
#define CIN      32
#define COUT     64
#define KVOL     27
#define OUT_X    11
#define OUT_Y    400
#define OUT_Z    352

// ---------------- device scratch (static, allocation-free) ----------------
__device__ int2 g_rules[(size_t)KVOL * NNZ];          // 47.7 MB rulebook
__device__ int  g_cnt[KVOL * 128];                    // counters, 512B apart
__device__ int  g_done;                               // gemm completion ctr

// ---------------- kernel A1: zero output (DRAM-write bound) ------------------
__global__ void zero_out(float4* __restrict__ out4, long long n4) {
    long long i = (long long)blockIdx.x * blockDim.x + threadIdx.x;
    long long step = (long long)gridDim.x * blockDim.x;
    float4 z = make_float4(0.f, 0.f, 0.f, 0.f);
    for (; i < n4; i += step) out4[i] = z;
}

// ---------------- kernel A2: build rulebook (warp-aggregated atomics) --------
__global__ void build_rules(const int* __restrict__ coords) {
    int i    = blockIdx.x * blockDim.x + threadIdx.x;
    int lane = threadIdx.x & 31;
    bool active = (i < NNZ);

    int cx = 0, cy = 0, cz = 0;
    if (active) {
        cx = coords[i * 3 + 0];
        cy = coords[i * 3 + 1];
        cz = coords[i * 3 + 2];
    }

    bool vX[3], vY[3], vZ[3];
    int  qX[3], qY[3], qZ[3];
#pragma unroll
    for (int o = 0; o < 3; o++) {
        int ox = cx + 1 - o; vX[o] = (ox >= 0) && !(ox & 1) && ((ox >> 1) < OUT_X); qX[o] = ox >> 1;
        int oy = cy + 1 - o; vY[o] = (oy >= 0) && !(oy & 1) && ((oy >> 1) < OUT_Y); qY[o] = oy >> 1;
        int oz = cz + 1 - o; vZ[o] = (oz >= 0) && !(oz & 1) && ((oz >> 1) < OUT_Z); qZ[o] = oz >> 1;
    }

#pragma unroll
    for (int kx = 0; kx < 3; kx++) {
#pragma unroll
        for (int ky = 0; ky < 3; ky++) {
#pragma unroll
            for (int kz = 0; kz < 3; kz++) {
                int k = (kx * 3 + ky) * 3 + kz;
                bool valid = active && vX[kx] && vY[ky] && vZ[kz];
                int flat = 0;
                if (valid) flat = (qX[kx] * OUT_Y + qY[ky]) * OUT_Z + qZ[kz];

                unsigned mask = __ballot_sync(0xffffffffu, valid);
                if (mask) {
                    int leader = __ffs(mask) - 1;
                    int base = 0;
                    if (lane == leader)
                        base = atomicAdd(&g_cnt[k * 128], __popc(mask));
                    base = __shfl_sync(0xffffffffu, base, leader);
                    if (valid) {
                        int pos = base + __popc(mask & ((1u << lane) - 1u));
                        g_rules[(size_t)k * NNZ + pos] = make_int2(i, flat);
                    }
                }
            }
        }
    }
}

// ---------------- kernel B: tf32 MMA, 3-deep cp.async pipeline ---------------
// Block 256 = 8 warps, tile = 64 points x 64 couts, ~7 tiles/block (GX=64).
// W[k] staged once into shared (tf32). Features flow via a 4-buffer / 3-deep
// cp.async pipeline: ONE __syncthreads per tile (issue into buf (i+3)&3 is
// race-free: its last readers finished before this iteration's entry sync).
// fp32->tf32 conversion at A-fragment load. Scatter: paired C columns ->
// red.global.add.v4.f32. Epilogue resets counters for the next replay.
#define TILE_P  64
#define GEMM_GX 64

#define MMA_TF32(c0,c1,c2,c3, a0,a1,a2,a3, b0,b1) \
    asm("mma.sync.aligned.m16n8k8.row.col.f32.tf32.tf32.f32 " \
        "{%0,%1,%2,%3}, {%4,%5,%6,%7}, {%8,%9}, {%0,%1,%2,%3};" \
        : "+f"(c0), "+f"(c1), "+f"(c2), "+f"(c3) \
        : "r"(a0), "r"(a1), "r"(a2), "r"(a3), "r"(b0), "r"(b1))

__device__ __forceinline__ unsigned f2tf32(float f) {
    unsigned u;
    asm("cvt.rna.tf32.f32 %0, %1;" : "=r"(u) : "f"(f));
    return u;
}

__device__ __forceinline__ void cp16(unsigned smem, const void* gmem) {
    asm volatile("cp.async.ca.shared.global [%0], [%1], 16;"
                 :: "r"(smem), "l"(gmem));
}
#define CP_COMMIT() asm volatile("cp.async.commit_group;")
#define CP_WAIT0()  asm volatile("cp.async.wait_group 0;")
#define CP_WAIT1()  asm volatile("cp.async.wait_group 1;")
#define CP_WAIT2()  asm volatile("cp.async.wait_group 2;")

__global__ __launch_bounds__(256)
void gather_gemm_scatter(const float* __restrict__ features,
                         const float* __restrict__ weight,
                         float* __restrict__ out) {
    const int k   = blockIdx.y;
    const int cnt = g_cnt[k * 128];

    const int tid  = threadIdx.x;
    const int w    = tid >> 5;
    const int lane = tid & 31;
    const int g    = lane >> 2;      // group id: A rows / B cols
    const int t    = lane & 3;       // thread-in-group: A cols / B rows
    const int slab = w & 3;
    const int half = w >> 2;

    __shared__ unsigned swt[CIN * COUT];          // tf32 weights, 8KB
    __shared__ float    sfu[4][TILE_P * 36];      // fp32 features, 4 buffers
    __shared__ int      sflat[4][TILE_P];

    // number of tiles this block owns
    int nt = 0;
    {
        int tiles = (cnt + TILE_P - 1) / TILE_P;
        if ((int)blockIdx.x < tiles)
            nt = (tiles - blockIdx.x + GEMM_GX - 1) / GEMM_GX;
    }

    if (nt > 0) {
        // ---- stage W[k] into shared (coalesced), convert to tf32 -----------
        {
            const float4* wk4 = (const float4*)(weight + (size_t)k * (CIN * COUT));
#pragma unroll
            for (int e = tid; e < CIN * COUT / 4; e += 256) {
                float4 v = wk4[e];
                swt[e * 4 + 0] = f2tf32(v.x);
                swt[e * 4 + 1] = f2tf32(v.y);
                swt[e * 4 + 2] = f2tf32(v.z);
                swt[e * 4 + 3] = f2tf32(v.w);
            }
        }

        const int2* rules_k = g_rules + (size_t)k * NNZ;
        const int p0 = tid >> 3;              // rows this thread stages
        const int p1 = 32 + (tid >> 3);
        const int c4 = tid & 7;               // 16B chunk within row

        auto issue_tile = [&](int i) {        // load rules + issue cp.async
            int buf  = i & 3;
            int base = (blockIdx.x + i * GEMM_GX) * TILE_P;
            int ja = base + p0; if (ja >= cnt) ja = cnt - 1;
            int jb = base + p1; if (jb >= cnt) jb = cnt - 1;
            int2 ra = __ldg(&rules_k[ja]);
            int2 rb = __ldg(&rules_k[jb]);
            unsigned sb = (unsigned)__cvta_generic_to_shared(&sfu[buf][0]);
            cp16(sb + (p0 * 36 + c4 * 4) * 4,
                 features + (size_t)ra.x * CIN + c4 * 4);
            cp16(sb + (p1 * 36 + c4 * 4) * 4,
                 features + (size_t)rb.x * CIN + c4 * 4);
            if (c4 == 0) { sflat[buf][p0] = ra.y; sflat[buf][p1] = rb.y; }
        };

        // ---- prolog: issue up to 3 tiles -----------------------------------
        int issued = (nt < 3) ? nt : 3;
        for (int i = 0; i < issued; i++) { issue_tile(i); CP_COMMIT(); }
        __syncthreads();   // swt ready (also joins prolog sflat writes)

        // ---- B fragments from shared ---------------------------------------
        unsigned B0[4][4], B1[4][4];
#pragma unroll
        for (int j = 0; j < 4; j++) {
            int n = half * 32 + j * 8 + g;
#pragma unroll
            for (int kk = 0; kk < 4; kk++) {
                int k0 = kk * 8 + t;
                B0[j][kk] = swt[k0 * COUT + n];
                B1[j][kk] = swt[(k0 + 4) * COUT + n];
            }
        }

        const int r0 = slab * 16 + g;         // local rows r0, r0+8

        for (int i = 0; i < nt; i++) {
            const int buf = i & 3;

            int pend = issued - i - 1;        // groups allowed to stay pending
            if (pend >= 2)      CP_WAIT2();
            else if (pend == 1) CP_WAIT1();
            else                CP_WAIT0();
            __syncthreads();                  // buf ready for all threads

            // ---- MMA: 16 rows x 32 couts per warp ---------------------------
            float C0[4], C1[4], C2[4], C3[4];
#pragma unroll
            for (int j = 0; j < 4; j++) { C0[j] = C1[j] = C2[j] = C3[j] = 0.f; }

            const float* fb = sfu[buf];
#pragma unroll
            for (int kk = 0; kk < 4; kk++) {
                int cbase = kk * 8 + t;
                unsigned a0 = f2tf32(fb[r0 * 36 + cbase]);
                unsigned a1 = f2tf32(fb[(r0 + 8) * 36 + cbase]);
                unsigned a2 = f2tf32(fb[r0 * 36 + cbase + 4]);
                unsigned a3 = f2tf32(fb[(r0 + 8) * 36 + cbase + 4]);
#pragma unroll
                for (int j = 0; j < 4; j++)
                    MMA_TF32(C0[j], C1[j], C2[j], C3[j],
                             a0, a1, a2, a3, B0[j][kk], B1[j][kk]);
            }

            // ---- scatter: pair columns -> red.v4 ----------------------------
            const int  base = (blockIdx.x + i * GEMM_GX) * TILE_P;
            const bool v0 = (base + r0)     < cnt;
            const bool v1 = (base + r0 + 8) < cnt;
            const int  f0 = sflat[buf][r0];
            const int  f1 = sflat[buf][r0 + 8];
            const int  colbase = half * 32 + 2 * t;
#pragma unroll
            for (int j = 0; j < 4; j++) {
                float x0 = __shfl_down_sync(0xffffffffu, C0[j], 1);
                float x1 = __shfl_down_sync(0xffffffffu, C1[j], 1);
                float x2 = __shfl_down_sync(0xffffffffu, C2[j], 1);
                float x3 = __shfl_down_sync(0xffffffffu, C3[j], 1);
                if ((t & 1) == 0) {
                    if (v0) {
                        const float* dst = out + (size_t)f0 * COUT + colbase + j * 8;
                        asm volatile(
                            "{ .reg .u64 pg; cvta.to.global.u64 pg, %0;\n\t"
                            "  red.global.add.v4.f32 [pg], {%1, %2, %3, %4}; }"
                            :: "l"(dst), "f"(C0[j]), "f"(C1[j]), "f"(x0), "f"(x1)
                            : "memory");
                    }
                    if (v1) {
                        const float* dst = out + (size_t)f1 * COUT + colbase + j * 8;
                        asm volatile(
                            "{ .reg .u64 pg; cvta.to.global.u64 pg, %0;\n\t"
                            "  red.global.add.v4.f32 [pg], {%1, %2, %3, %4}; }"
                            :: "l"(dst), "f"(C2[j]), "f"(C3[j]), "f"(x2), "f"(x3)
                            : "memory");
                    }
                }
            }

            // issue tile i+3 into buf (i+3)&3: its last readers (iter i-1)
            // finished before this iteration's entry sync. No extra barrier.
            if (i + 3 < nt) { issue_tile(i + 3); CP_COMMIT(); issued++; }
        }
    }

    // ---- epilogue: last finished block resets counters for next replay -----
    __syncthreads();
    if (tid == 0) {
        int d = atomicAdd(&g_done, 1);
        if (d == GEMM_GX * KVOL - 1) {
#pragma unroll
            for (int i = 0; i < KVOL; i++) g_cnt[i * 128] = 0;
            g_done = 0;
        }
    }
}

// ---------------- launch: fork zero (s1) vs build (default), join, GEMM ------
extern "C" void kernel_launch(void* const* d_in, const int* in_sizes, int n_in,
                              void* d_out, int out_size) {
    const float* features = (const float*)d_in[0];
    const int*   coords   = (const int*)d_in[1];
    const float* weight   = (const float*)d_in[2];
    float*       out      = (float*)d_out;

    static cudaStream_t s1 = nullptr;
    static cudaEvent_t ev_fork = nullptr, ev_join = nullptr;
    if (s1 == nullptr) {
        cudaStreamCreateWithFlags(&s1, cudaStreamNonBlocking);
        cudaEventCreateWithFlags(&ev_fork, cudaEventDisableTiming);
        cudaEventCreateWithFlags(&ev_join, cudaEventDisableTiming);
    }

    long long n4 = (long long)out_size / 4;

    // fork: zero on s1, build on the capture (default) stream, concurrently
    cudaEventRecord(ev_fork, 0);
    cudaStreamWaitEvent(s1, ev_fork, 0);
    zero_out<<<4096, 256, 0, s1>>>((float4*)out, n4);
    cudaEventRecord(ev_join, s1);

    build_rules<<<(NNZ + 255) / 256, 256>>>(coords);

    // join: GEMM needs both the rulebook and the zeroed output
    cudaStreamWaitEvent(0, ev_join, 0);
    dim3 grid(GEMM_GX, KVOL);
    gather_gemm_scatter<<<grid, 256>>>(features, weight, out);
}

// round 12
// speedup vs baseline: 1.0792x; 1.0792x over previous
#include <cuda_runtime.h>
#include <cstdint>

// ---------------- problem constants ----------------
#define NNZ      220939
#define CIN      32
#define COUT     64
#define KVOL     27
#define OUT_X    11
#define OUT_Y    400
#define OUT_Z    352

// ---------------- device scratch (static, allocation-free) ----------------
__device__ int2 g_rules[(size_t)KVOL * NNZ];          // 47.7 MB rulebook
__device__ int  g_cnt[KVOL * 128];                    // counters, 512B apart
__device__ int  g_done;                               // gemm completion ctr

// ---------------- kernel A: fused zero + build, BUILD-FIRST ------------------
// Build blocks are blockIdx 0..863: they enter wave 1 alongside the first
// zero blocks and finish inside the zero stream (measured-best ordering, R4).
#define BUILD_BLOCKS 864   // ceil(NNZ/256)
#define ZERO_BLOCKS  4096

__global__ void zero_and_build(float4* __restrict__ out4, long long n4,
                               const int* __restrict__ coords) {
    if (blockIdx.x >= BUILD_BLOCKS) {
        long long i = (long long)(blockIdx.x - BUILD_BLOCKS) * blockDim.x + threadIdx.x;
        long long step = (long long)ZERO_BLOCKS * blockDim.x;
        float4 z = make_float4(0.f, 0.f, 0.f, 0.f);
        for (; i < n4; i += step) out4[i] = z;
        return;
    }

    int i    = blockIdx.x * blockDim.x + threadIdx.x;
    int lane = threadIdx.x & 31;
    bool active = (i < NNZ);

    int cx = 0, cy = 0, cz = 0;
    if (active) {
        cx = coords[i * 3 + 0];
        cy = coords[i * 3 + 1];
        cz = coords[i * 3 + 2];
    }

    bool vX[3], vY[3], vZ[3];
    int  qX[3], qY[3], qZ[3];
#pragma unroll
    for (int o = 0; o < 3; o++) {
        int ox = cx + 1 - o; vX[o] = (ox >= 0) && !(ox & 1) && ((ox >> 1) < OUT_X); qX[o] = ox >> 1;
        int oy = cy + 1 - o; vY[o] = (oy >= 0) && !(oy & 1) && ((oy >> 1) < OUT_Y); qY[o] = oy >> 1;
        int oz = cz + 1 - o; vZ[o] = (oz >= 0) && !(oz & 1) && ((oz >> 1) < OUT_Z); qZ[o] = oz >> 1;
    }

#pragma unroll
    for (int kx = 0; kx < 3; kx++) {
#pragma unroll
        for (int ky = 0; ky < 3; ky++) {
#pragma unroll
            for (int kz = 0; kz < 3; kz++) {
                int k = (kx * 3 + ky) * 3 + kz;
                bool valid = active && vX[kx] && vY[ky] && vZ[kz];
                int flat = 0;
                if (valid) flat = (qX[kx] * OUT_Y + qY[ky]) * OUT_Z + qZ[kz];

                unsigned mask = __ballot_sync(0xffffffffu, valid);
                if (mask) {
                    int leader = __ffs(mask) - 1;
                    int base = 0;
                    if (lane == leader)
                        base = atomicAdd(&g_cnt[k * 128], __popc(mask));
                    base = __shfl_sync(0xffffffffu, base, leader);
                    if (valid) {
                        int pos = base + __popc(mask & ((1u << lane) - 1u));
                        g_rules[(size_t)k * NNZ + pos] = make_int2(i, flat);
                    }
                }
            }
        }
    }
}

// ---------------- kernel B: tf32 MMA, 3-deep cp.async pipeline ---------------
// Block 256 = 8 warps, tile = 64 points x 64 couts, ~7 tiles/block (GX=64).
// W[k] staged once into shared (tf32). 4-buffer / 3-deep cp.async pipeline,
// ONE __syncthreads per tile. Rules for tile i+3 are prefetched into
// registers at the TOP of iteration i (LDG latency hides under wait+MMA+
// scatter); the feature cp.async issue happens after the scatter into buffer
// (i+3)&3, whose last readers finished before this iteration's entry sync.
// Scatter: paired C columns -> red.global.add.v4.f32. Epilogue resets
// counters for the next graph replay.
#define TILE_P  64
#define GEMM_GX 64

#define MMA_TF32(c0,c1,c2,c3, a0,a1,a2,a3, b0,b1) \
    asm("mma.sync.aligned.m16n8k8.row.col.f32.tf32.tf32.f32 " \
        "{%0,%1,%2,%3}, {%4,%5,%6,%7}, {%8,%9}, {%0,%1,%2,%3};" \
        : "+f"(c0), "+f"(c1), "+f"(c2), "+f"(c3) \
        : "r"(a0), "r"(a1), "r"(a2), "r"(a3), "r"(b0), "r"(b1))

__device__ __forceinline__ unsigned f2tf32(float f) {
    unsigned u;
    asm("cvt.rna.tf32.f32 %0, %1;" : "=r"(u) : "f"(f));
    return u;
}

__device__ __forceinline__ void cp16(unsigned smem, const void* gmem) {
    asm volatile("cp.async.ca.shared.global [%0], [%1], 16;"
                 :: "r"(smem), "l"(gmem));
}
#define CP_COMMIT() asm volatile("cp.async.commit_group;")
#define CP_WAIT0()  asm volatile("cp.async.wait_group 0;")
#define CP_WAIT1()  asm volatile("cp.async.wait_group 1;")
#define CP_WAIT2()  asm volatile("cp.async.wait_group 2;")

__global__ __launch_bounds__(256)
void gather_gemm_scatter(const float* __restrict__ features,
                         const float* __restrict__ weight,
                         float* __restrict__ out) {
    const int k   = blockIdx.y;
    const int cnt = g_cnt[k * 128];

    const int tid  = threadIdx.x;
    const int w    = tid >> 5;
    const int lane = tid & 31;
    const int g    = lane >> 2;      // group id: A rows / B cols
    const int t    = lane & 3;       // thread-in-group: A cols / B rows
    const int slab = w & 3;
    const int half = w >> 2;

    __shared__ unsigned swt[CIN * COUT];          // tf32 weights, 8KB
    __shared__ float    sfu[4][TILE_P * 36];      // fp32 features, 4 buffers
    __shared__ int      sflat[4][TILE_P];

    // number of tiles this block owns
    int nt = 0;
    {
        int tiles = (cnt + TILE_P - 1) / TILE_P;
        if ((int)blockIdx.x < tiles)
            nt = (tiles - blockIdx.x + GEMM_GX - 1) / GEMM_GX;
    }

    if (nt > 0) {
        // ---- stage W[k] into shared (coalesced), convert to tf32 -----------
        {
            const float4* wk4 = (const float4*)(weight + (size_t)k * (CIN * COUT));
#pragma unroll
            for (int e = tid; e < CIN * COUT / 4; e += 256) {
                float4 v = wk4[e];
                swt[e * 4 + 0] = f2tf32(v.x);
                swt[e * 4 + 1] = f2tf32(v.y);
                swt[e * 4 + 2] = f2tf32(v.z);
                swt[e * 4 + 3] = f2tf32(v.w);
            }
        }

        const int2* rules_k = g_rules + (size_t)k * NNZ;
        const int p0 = tid >> 3;              // rows this thread stages
        const int p1 = 32 + (tid >> 3);
        const int c4 = tid & 7;               // 16B chunk within row

        auto load_rules = [&](int i, int2& ra, int2& rb) {
            int base = (blockIdx.x + i * GEMM_GX) * TILE_P;
            int ja = base + p0; if (ja >= cnt) ja = cnt - 1;
            int jb = base + p1; if (jb >= cnt) jb = cnt - 1;
            ra = __ldg(&rules_k[ja]);
            rb = __ldg(&rules_k[jb]);
        };
        auto issue_feat = [&](int buf, int2 ra, int2 rb) {
            unsigned sb = (unsigned)__cvta_generic_to_shared(&sfu[buf][0]);
            cp16(sb + (p0 * 36 + c4 * 4) * 4,
                 features + (size_t)ra.x * CIN + c4 * 4);
            cp16(sb + (p1 * 36 + c4 * 4) * 4,
                 features + (size_t)rb.x * CIN + c4 * 4);
            if (c4 == 0) { sflat[buf][p0] = ra.y; sflat[buf][p1] = rb.y; }
        };

        // ---- prolog: issue up to 3 tiles -----------------------------------
        int issued = (nt < 3) ? nt : 3;
        for (int i = 0; i < issued; i++) {
            int2 ra, rb;
            load_rules(i, ra, rb);
            issue_feat(i & 3, ra, rb);
            CP_COMMIT();
        }
        __syncthreads();   // swt ready (also joins prolog sflat writes)

        // ---- B fragments from shared ---------------------------------------
        unsigned B0[4][4], B1[4][4];
#pragma unroll
        for (int j = 0; j < 4; j++) {
            int n = half * 32 + j * 8 + g;
#pragma unroll
            for (int kk = 0; kk < 4; kk++) {
                int k0 = kk * 8 + t;
                B0[j][kk] = swt[k0 * COUT + n];
                B1[j][kk] = swt[(k0 + 4) * COUT + n];
            }
        }

        const int r0 = slab * 16 + g;         // local rows r0, r0+8

        for (int i = 0; i < nt; i++) {
            const int buf = i & 3;

            // rules for tile i+3 FIRST: LDG latency hides under wait+compute
            const bool has3 = (i + 3 < nt);
            int2 ra, rb;
            if (has3) load_rules(i + 3, ra, rb);

            int pend = issued - i - 1;        // groups allowed to stay pending
            if (pend >= 2)      CP_WAIT2();
            else if (pend == 1) CP_WAIT1();
            else                CP_WAIT0();
            __syncthreads();                  // buf ready for all threads

            // ---- MMA: 16 rows x 32 couts per warp ---------------------------
            float C0[4], C1[4], C2[4], C3[4];
#pragma unroll
            for (int j = 0; j < 4; j++) { C0[j] = C1[j] = C2[j] = C3[j] = 0.f; }

            const float* fb = sfu[buf];
#pragma unroll
            for (int kk = 0; kk < 4; kk++) {
                int cbase = kk * 8 + t;
                unsigned a0 = f2tf32(fb[r0 * 36 + cbase]);
                unsigned a1 = f2tf32(fb[(r0 + 8) * 36 + cbase]);
                unsigned a2 = f2tf32(fb[r0 * 36 + cbase + 4]);
                unsigned a3 = f2tf32(fb[(r0 + 8) * 36 + cbase + 4]);
#pragma unroll
                for (int j = 0; j < 4; j++)
                    MMA_TF32(C0[j], C1[j], C2[j], C3[j],
                             a0, a1, a2, a3, B0[j][kk], B1[j][kk]);
            }

            // ---- scatter: pair columns -> red.v4 ----------------------------
            const int  base = (blockIdx.x + i * GEMM_GX) * TILE_P;
            const bool v0 = (base + r0)     < cnt;
            const bool v1 = (base + r0 + 8) < cnt;
            const int  f0 = sflat[buf][r0];
            const int  f1 = sflat[buf][r0 + 8];
            const int  colbase = half * 32 + 2 * t;
#pragma unroll
            for (int j = 0; j < 4; j++) {
                float x0 = __shfl_down_sync(0xffffffffu, C0[j], 1);
                float x1 = __shfl_down_sync(0xffffffffu, C1[j], 1);
                float x2 = __shfl_down_sync(0xffffffffu, C2[j], 1);
                float x3 = __shfl_down_sync(0xffffffffu, C3[j], 1);
                if ((t & 1) == 0) {
                    if (v0) {
                        const float* dst = out + (size_t)f0 * COUT + colbase + j * 8;
                        asm volatile(
                            "{ .reg .u64 pg; cvta.to.global.u64 pg, %0;\n\t"
                            "  red.global.add.v4.f32 [pg], {%1, %2, %3, %4}; }"
                            :: "l"(dst), "f"(C0[j]), "f"(C1[j]), "f"(x0), "f"(x1)
                            : "memory");
                    }
                    if (v1) {
                        const float* dst = out + (size_t)f1 * COUT + colbase + j * 8;
                        asm volatile(
                            "{ .reg .u64 pg; cvta.to.global.u64 pg, %0;\n\t"
                            "  red.global.add.v4.f32 [pg], {%1, %2, %3, %4}; }"
                            :: "l"(dst), "f"(C2[j]), "f"(C3[j]), "f"(x2), "f"(x3)
                            : "memory");
                    }
                }
            }

            // issue tile i+3 into buf (i+3)&3: its last readers (iter i-1)
            // finished before this iteration's entry sync. No extra barrier.
            if (has3) { issue_feat((i + 3) & 3, ra, rb); CP_COMMIT(); issued++; }
        }
    }

    // ---- epilogue: last finished block resets counters for next replay -----
    __syncthreads();
    if (tid == 0) {
        int d = atomicAdd(&g_done, 1);
        if (d == GEMM_GX * KVOL - 1) {
#pragma unroll
            for (int i = 0; i < KVOL; i++) g_cnt[i * 128] = 0;
            g_done = 0;
        }
    }
}

// ---------------- launch ----------------
extern "C" void kernel_launch(void* const* d_in, const int* in_sizes, int n_in,
                              void* d_out, int out_size) {
    const float* features = (const float*)d_in[0];
    const int*   coords   = (const int*)d_in[1];
    const float* weight   = (const float*)d_in[2];
    float*       out      = (float*)d_out;

    long long n4 = (long long)out_size / 4;
    zero_and_build<<<BUILD_BLOCKS + ZERO_BLOCKS, 256>>>((float4*)out, n4, coords);

    dim3 grid(GEMM_GX, KVOL);
    gather_gemm_scatter<<<grid, 256>>>(features, weight, out);
}